// round 10
// baseline (speedup 1.0000x reference)
#include <cuda_runtime.h>
#include <math.h>

#define BB 64
#define NN 17
#define CC 32
#define HW 4096   // 64*64

#define OFF_J 0           // joints: 64*17*2 = 2176
#define OFF_V 2176        // valid:  64*17   = 1088
#define OFF_K 3264        // new_keys: 64*17*32 = 34816
#define OFF_D 38080       // dist_x4: 64*17*256*256 = 71303168

__device__ float g_wdist[(size_t)BB * NN * HW];

// Analytic weight map (empirically identical to the literal 15-move loop)
__device__ __forceinline__ float weight_at(int x, int y, int kx, int ky) {
    int dx = abs(x - kx), dy = abs(y - ky);
    int m = 0;
    int mc = (dx > 0) ? dx : ((kx == 0 || kx == 63) ? 1 : 0);
    if (mc >= 1 && mc <= 15 && dy <= mc) m = mc;
    int mr = (dy > 0) ? dy : ((ky == 0 || ky == 63) ? 1 : 0);
    if (mr >= 1 && mr <= 15 && dx <= mr && mr > m) m = mr;
    return m ? (0.5f + 0.25f * (float)m) : 10.0f;
}

// ---------------- Kernel A: wdist (B,N,64,64) ----------------
// C-tiled accumulation: 17 dot accumulators, 8-wide q tile -> ~40 regs,
// 256-thr blocks -> 5+ blocks/SM for DRAM latency hiding. fmaf chains stay
// strictly ascending-c per n => bit-identical to the monolithic version.
__global__ void __launch_bounds__(256) kA(const float* __restrict__ q,
                                          const float* __restrict__ keys,
                                          const int*   __restrict__ joints) {
    const int b = blockIdx.y;
    const int p = blockIdx.x * 256 + threadIdx.x;   // pixel in [0,4096)
    __shared__ __align__(16) float skey[NN][CC];
    __shared__ float sk2[NN];
    __shared__ int   skx[NN], sky[NN];
    const int t = threadIdx.x;
    if (t < NN * CC / 4)
        reinterpret_cast<float4*>(skey)[t] =
            reinterpret_cast<const float4*>(keys + b * NN * CC)[t];
    __syncthreads();
    if (t < NN) {
        float s = 0.f;   // mul+add sequential, no fma (XLA-faithful)
        for (int c = 0; c < CC; c++) s = __fadd_rn(s, __fmul_rn(skey[t][c], skey[t][c]));
        sk2[t] = s;
        skx[t] = joints[(b * NN + t) * 2 + 0];
        sky[t] = joints[(b * NN + t) * 2 + 1];
    }
    __syncthreads();

    const float* qb = q + (size_t)b * CC * HW + p;

    float acc[NN];
#pragma unroll
    for (int n = 0; n < NN; n++) acc[n] = 0.f;
    float q2 = 0.f;

#pragma unroll
    for (int ct = 0; ct < CC / 8; ct++) {          // 4 tiles of 8 channels
        float qv[8];
#pragma unroll
        for (int j = 0; j < 8; j++) {
            qv[j] = qb[(size_t)(ct * 8 + j) * HW];
            q2 = __fadd_rn(q2, __fmul_rn(qv[j], qv[j]));   // ascending c
        }
#pragma unroll 1
        for (int n = 0; n < NN; n++) {
            const float4* k4 = reinterpret_cast<const float4*>(skey[n] + ct * 8);
            float4 ka = k4[0], kb = k4[1];                 // 2x LDS.128
            float d = acc[n];                              // ascending-c fmaf
            d = fmaf(ka.x, qv[0], d);
            d = fmaf(ka.y, qv[1], d);
            d = fmaf(ka.z, qv[2], d);
            d = fmaf(ka.w, qv[3], d);
            d = fmaf(kb.x, qv[4], d);
            d = fmaf(kb.y, qv[5], d);
            d = fmaf(kb.z, qv[6], d);
            d = fmaf(kb.w, qv[7], d);
            acc[n] = d;
        }
    }

    const int y = p >> 6, x = p & 63;
    float* wout = g_wdist + ((size_t)b * NN) * HW + p;
#pragma unroll 1
    for (int n = 0; n < NN; n++) {
        float d2 = __fsub_rn(__fadd_rn(q2, sk2[n]), __fmul_rn(2.0f, acc[n]));
        float dist = sqrtf(fmaxf(d2, 0.0f));
        float wm = weight_at(x, y, skx[n], sky[n]);
        wout[(size_t)n * HW] = __fmul_rn(dist, wm);
    }
}

// ---------------- Kernel B: upsample + argmins + outputs ---------------- (round-6 exact)
__global__ void __launch_bounds__(256, 8) kB(const float* __restrict__ q,
                                             const float* __restrict__ keys,
                                             float* __restrict__ out) {
    const int bn = blockIdx.x;          // b*17+n
    const int b  = bn / NN;
    const int t  = threadIdx.x;

    __shared__ float sw[64 * 64];
    __shared__ float rv[256];
    __shared__ int   ri[256];
    __shared__ int   s_idx0, s_valid;
    __shared__ float s_mind;

    // phase 1: load wdist, track min/argmin (first occurrence)
    const float* src = g_wdist + (size_t)bn * HW;
    float bv = 3.0e38f; int bi = 0;
    for (int k = 0; k < 16; k++) {
        int idx = k * 256 + t;          // ascending per-thread -> strict <
        float v = src[idx];
        sw[idx] = v;
        if (v < bv) { bv = v; bi = idx; }
    }
    rv[t] = bv; ri[t] = bi;
    __syncthreads();
    for (int s = 128; s > 0; s >>= 1) {
        if (t < s) {
            float v2 = rv[t + s]; int i2 = ri[t + s];
            if (v2 < rv[t] || (v2 == rv[t] && i2 < ri[t])) { rv[t] = v2; ri[t] = i2; }
        }
        __syncthreads();
    }
    if (t == 0) { s_mind = rv[0]; s_idx0 = ri[0]; }
    __syncthreads();

    // phase 2: 4x bilinear upsample, gemm-faithful scalar arithmetic
    float* od = out + OFF_D + (size_t)bn * 65536;
    float bv2 = 3.0e38f; int bi2 = 0;
    for (int it = 0; it < 16; it++) {
        int T = it * 256 + t;
        int ti = T >> 6, tj = T & 63;
        int yU = (ti > 0) ? ti - 1 : 0;
        int yD = (ti < 63) ? ti + 1 : 63;
        int xL = (tj > 0) ? tj - 1 : 0;
        int xR = (tj < 63) ? tj + 1 : 63;

        float up[3] = { sw[yU * 64 + xL], sw[yU * 64 + tj], sw[yU * 64 + xR] };
        float ce[3] = { sw[ti * 64 + xL], sw[ti * 64 + tj], sw[ti * 64 + xR] };
        float dn[3] = { sw[yD * 64 + xL], sw[yD * 64 + tj], sw[yD * 64 + xR] };

        float vy[4][3];
#pragma unroll
        for (int c3 = 0; c3 < 3; c3++) {
            if (ti == 0) { vy[0][c3] = ce[c3]; vy[1][c3] = ce[c3]; }
            else {
                vy[0][c3] = fmaf(0.625f, ce[c3], __fmul_rn(0.375f, up[c3]));
                vy[1][c3] = fmaf(0.875f, ce[c3], __fmul_rn(0.125f, up[c3]));
            }
            if (ti == 63) { vy[2][c3] = ce[c3]; vy[3][c3] = ce[c3]; }
            else {
                vy[2][c3] = fmaf(0.125f, dn[c3], __fmul_rn(0.875f, ce[c3]));
                vy[3][c3] = fmaf(0.375f, dn[c3], __fmul_rn(0.625f, ce[c3]));
            }
        }
#pragma unroll
        for (int r = 0; r < 4; r++) {
            float vL = vy[r][0], vC = vy[r][1], vR = vy[r][2];
            float o0, o1, o2, o3;
            if (tj == 0) { o0 = vC; o1 = vC; }
            else {
                o0 = fmaf(0.625f, vC, __fmul_rn(0.375f, vL));
                o1 = fmaf(0.875f, vC, __fmul_rn(0.125f, vL));
            }
            if (tj == 63) { o2 = vC; o3 = vC; }
            else {
                o2 = fmaf(0.125f, vR, __fmul_rn(0.875f, vC));
                o3 = fmaf(0.375f, vR, __fmul_rn(0.625f, vC));
            }
            int pbase = (4 * ti + r) * 256 + 4 * tj;
            *reinterpret_cast<float4*>(od + pbase) = make_float4(o0, o1, o2, o3);
            if (o0 < bv2) { bv2 = o0; bi2 = pbase; }
            if (o1 < bv2) { bv2 = o1; bi2 = pbase + 1; }
            if (o2 < bv2) { bv2 = o2; bi2 = pbase + 2; }
            if (o3 < bv2) { bv2 = o3; bi2 = pbase + 3; }
        }
    }

    __syncthreads();
    rv[t] = bv2; ri[t] = bi2;
    __syncthreads();
    for (int s = 128; s > 0; s >>= 1) {
        if (t < s) {
            float v2 = rv[t + s]; int i2 = ri[t + s];
            if (v2 < rv[t] || (v2 == rv[t] && i2 < ri[t])) { rv[t] = v2; ri[t] = i2; }
        }
        __syncthreads();
    }

    if (t == 0) {
        int sidx = ri[0];
        bool nonzero = false;
        for (int c = 0; c < CC; c++) nonzero |= (keys[bn * CC + c] != 0.0f);
        bool valid = nonzero && ((int)floorf(s_mind) <= 5);
        s_valid = valid ? 1 : 0;
        int sv = valid ? (sidx >> 8)  : -1;
        int sh = valid ? (sidx & 255) : -1;
        out[OFF_J + bn * 2 + 0] = (float)sv;
        out[OFF_J + bn * 2 + 1] = (float)sh;
        out[OFF_V + bn] = valid ? 1.0f : 0.0f;
    }
    __syncthreads();
    if (t < CC) {
        float nk = s_valid ? q[((size_t)b * CC + t) * HW + s_idx0]
                           : keys[bn * CC + t];
        out[OFF_K + bn * CC + t] = nk;
    }
}

extern "C" void kernel_launch(void* const* d_in, const int* in_sizes, int n_in,
                              void* d_out, int out_size) {
    const float* q      = (const float*)d_in[0];
    const float* keys   = (const float*)d_in[1];
    const int*   joints = (const int*)  d_in[2];
    float* out = (float*)d_out;

    dim3 gA(16, BB);
    kA<<<gA, 256>>>(q, keys, joints);
    kB<<<BB * NN, 256>>>(q, keys, out);
}

// round 11
// speedup vs baseline: 1.1040x; 1.1040x over previous
#include <cuda_runtime.h>
#include <math.h>

#define BB 64
#define NN 17
#define CC 32
#define HW 4096   // 64*64

#define OFF_J 0           // joints: 64*17*2 = 2176
#define OFF_V 2176        // valid:  64*17   = 1088
#define OFF_K 3264        // new_keys: 64*17*32 = 34816
#define OFF_D 38080       // dist_x4: 64*17*256*256 = 71303168

__device__ float g_wdist[(size_t)BB * NN * HW];

// Proven-equal simplification of the 15-move ring weight:
//   M = max(dx,dy); w = 0.5+0.25*M for 1<=M<=15;
//   M==0 -> 0.75 iff keypoint on any border else 10; M>15 -> 10.
__device__ __forceinline__ float weight_at(int x, int y, int kx, int ky) {
    int dx = abs(x - kx), dy = abs(y - ky);
    int M = max(dx, dy);
    bool border = (kx == 0) | (kx == 63) | (ky == 0) | (ky == 63);
    if (M == 0) return border ? 0.75f : 10.0f;
    return (M <= 15) ? fmaf(0.25f, (float)M, 0.5f) : 10.0f;
}

// ---------------- Kernel A: wdist (B,N,64,64) ----------------
// C-tiled (8-wide q tile) with FULLY UNROLLED n loops so acc[17] stays in
// registers (round-10's unroll-1 version spilled to local). fmaf chains are
// strictly ascending-c per n => bit-identical results.
__global__ void __launch_bounds__(256) kA(const float* __restrict__ q,
                                          const float* __restrict__ keys,
                                          const int*   __restrict__ joints) {
    const int b = blockIdx.y;
    const int p = blockIdx.x * 256 + threadIdx.x;   // pixel in [0,4096)
    __shared__ __align__(16) float skey[NN][CC];
    __shared__ float sk2[NN];
    __shared__ int   skx[NN], sky[NN];
    const int t = threadIdx.x;
    if (t < NN * CC / 4)
        reinterpret_cast<float4*>(skey)[t] =
            reinterpret_cast<const float4*>(keys + b * NN * CC)[t];
    __syncthreads();
    if (t < NN) {
        float s = 0.f;   // mul+add sequential, no fma (XLA-faithful)
        for (int c = 0; c < CC; c++) s = __fadd_rn(s, __fmul_rn(skey[t][c], skey[t][c]));
        sk2[t] = s;
        skx[t] = joints[(b * NN + t) * 2 + 0];
        sky[t] = joints[(b * NN + t) * 2 + 1];
    }
    __syncthreads();

    const float* qb = q + (size_t)b * CC * HW + p;

    float acc[NN];
#pragma unroll
    for (int n = 0; n < NN; n++) acc[n] = 0.f;
    float q2 = 0.f;

#pragma unroll
    for (int ct = 0; ct < CC / 8; ct++) {          // 4 tiles of 8 channels
        float qv[8];
#pragma unroll
        for (int j = 0; j < 8; j++) {
            qv[j] = qb[(size_t)(ct * 8 + j) * HW];
            q2 = __fadd_rn(q2, __fmul_rn(qv[j], qv[j]));   // ascending c
        }
#pragma unroll
        for (int n = 0; n < NN; n++) {             // UNROLLED: acc in regs
            const float4* k4 = reinterpret_cast<const float4*>(skey[n] + ct * 8);
            float4 ka = k4[0], kb = k4[1];         // 2x LDS.128 broadcast
            float d = acc[n];                      // ascending-c fmaf
            d = fmaf(ka.x, qv[0], d);
            d = fmaf(ka.y, qv[1], d);
            d = fmaf(ka.z, qv[2], d);
            d = fmaf(ka.w, qv[3], d);
            d = fmaf(kb.x, qv[4], d);
            d = fmaf(kb.y, qv[5], d);
            d = fmaf(kb.z, qv[6], d);
            d = fmaf(kb.w, qv[7], d);
            acc[n] = d;
        }
    }

    const int y = p >> 6, x = p & 63;
    float* wout = g_wdist + ((size_t)b * NN) * HW + p;
#pragma unroll
    for (int n = 0; n < NN; n++) {                 // UNROLLED: acc in regs
        float d2 = __fsub_rn(__fadd_rn(q2, sk2[n]), __fmul_rn(2.0f, acc[n]));
        float dist = sqrtf(fmaxf(d2, 0.0f));
        float wm = weight_at(x, y, skx[n], sky[n]);
        wout[(size_t)n * HW] = __fmul_rn(dist, wm);
    }
}

// ---------------- Kernel B: upsample + argmins + outputs ---------------- (round-6 exact)
__global__ void __launch_bounds__(256, 8) kB(const float* __restrict__ q,
                                             const float* __restrict__ keys,
                                             float* __restrict__ out) {
    const int bn = blockIdx.x;          // b*17+n
    const int b  = bn / NN;
    const int t  = threadIdx.x;

    __shared__ float sw[64 * 64];
    __shared__ float rv[256];
    __shared__ int   ri[256];
    __shared__ int   s_idx0, s_valid;
    __shared__ float s_mind;

    // phase 1: load wdist, track min/argmin (first occurrence)
    const float* src = g_wdist + (size_t)bn * HW;
    float bv = 3.0e38f; int bi = 0;
    for (int k = 0; k < 16; k++) {
        int idx = k * 256 + t;          // ascending per-thread -> strict <
        float v = src[idx];
        sw[idx] = v;
        if (v < bv) { bv = v; bi = idx; }
    }
    rv[t] = bv; ri[t] = bi;
    __syncthreads();
    for (int s = 128; s > 0; s >>= 1) {
        if (t < s) {
            float v2 = rv[t + s]; int i2 = ri[t + s];
            if (v2 < rv[t] || (v2 == rv[t] && i2 < ri[t])) { rv[t] = v2; ri[t] = i2; }
        }
        __syncthreads();
    }
    if (t == 0) { s_mind = rv[0]; s_idx0 = ri[0]; }
    __syncthreads();

    // phase 2: 4x bilinear upsample, gemm-faithful scalar arithmetic
    float* od = out + OFF_D + (size_t)bn * 65536;
    float bv2 = 3.0e38f; int bi2 = 0;
    for (int it = 0; it < 16; it++) {
        int T = it * 256 + t;
        int ti = T >> 6, tj = T & 63;
        int yU = (ti > 0) ? ti - 1 : 0;
        int yD = (ti < 63) ? ti + 1 : 63;
        int xL = (tj > 0) ? tj - 1 : 0;
        int xR = (tj < 63) ? tj + 1 : 63;

        float up[3] = { sw[yU * 64 + xL], sw[yU * 64 + tj], sw[yU * 64 + xR] };
        float ce[3] = { sw[ti * 64 + xL], sw[ti * 64 + tj], sw[ti * 64 + xR] };
        float dn[3] = { sw[yD * 64 + xL], sw[yD * 64 + tj], sw[yD * 64 + xR] };

        float vy[4][3];
#pragma unroll
        for (int c3 = 0; c3 < 3; c3++) {
            if (ti == 0) { vy[0][c3] = ce[c3]; vy[1][c3] = ce[c3]; }
            else {
                vy[0][c3] = fmaf(0.625f, ce[c3], __fmul_rn(0.375f, up[c3]));
                vy[1][c3] = fmaf(0.875f, ce[c3], __fmul_rn(0.125f, up[c3]));
            }
            if (ti == 63) { vy[2][c3] = ce[c3]; vy[3][c3] = ce[c3]; }
            else {
                vy[2][c3] = fmaf(0.125f, dn[c3], __fmul_rn(0.875f, ce[c3]));
                vy[3][c3] = fmaf(0.375f, dn[c3], __fmul_rn(0.625f, ce[c3]));
            }
        }
#pragma unroll
        for (int r = 0; r < 4; r++) {
            float vL = vy[r][0], vC = vy[r][1], vR = vy[r][2];
            float o0, o1, o2, o3;
            if (tj == 0) { o0 = vC; o1 = vC; }
            else {
                o0 = fmaf(0.625f, vC, __fmul_rn(0.375f, vL));
                o1 = fmaf(0.875f, vC, __fmul_rn(0.125f, vL));
            }
            if (tj == 63) { o2 = vC; o3 = vC; }
            else {
                o2 = fmaf(0.125f, vR, __fmul_rn(0.875f, vC));
                o3 = fmaf(0.375f, vR, __fmul_rn(0.625f, vC));
            }
            int pbase = (4 * ti + r) * 256 + 4 * tj;
            *reinterpret_cast<float4*>(od + pbase) = make_float4(o0, o1, o2, o3);
            if (o0 < bv2) { bv2 = o0; bi2 = pbase; }
            if (o1 < bv2) { bv2 = o1; bi2 = pbase + 1; }
            if (o2 < bv2) { bv2 = o2; bi2 = pbase + 2; }
            if (o3 < bv2) { bv2 = o3; bi2 = pbase + 3; }
        }
    }

    __syncthreads();
    rv[t] = bv2; ri[t] = bi2;
    __syncthreads();
    for (int s = 128; s > 0; s >>= 1) {
        if (t < s) {
            float v2 = rv[t + s]; int i2 = ri[t + s];
            if (v2 < rv[t] || (v2 == rv[t] && i2 < ri[t])) { rv[t] = v2; ri[t] = i2; }
        }
        __syncthreads();
    }

    if (t == 0) {
        int sidx = ri[0];
        bool nonzero = false;
        for (int c = 0; c < CC; c++) nonzero |= (keys[bn * CC + c] != 0.0f);
        bool valid = nonzero && ((int)floorf(s_mind) <= 5);
        s_valid = valid ? 1 : 0;
        int sv = valid ? (sidx >> 8)  : -1;
        int sh = valid ? (sidx & 255) : -1;
        out[OFF_J + bn * 2 + 0] = (float)sv;
        out[OFF_J + bn * 2 + 1] = (float)sh;
        out[OFF_V + bn] = valid ? 1.0f : 0.0f;
    }
    __syncthreads();
    if (t < CC) {
        float nk = s_valid ? q[((size_t)b * CC + t) * HW + s_idx0]
                           : keys[bn * CC + t];
        out[OFF_K + bn * CC + t] = nk;
    }
}

extern "C" void kernel_launch(void* const* d_in, const int* in_sizes, int n_in,
                              void* d_out, int out_size) {
    const float* q      = (const float*)d_in[0];
    const float* keys   = (const float*)d_in[1];
    const int*   joints = (const int*)  d_in[2];
    float* out = (float*)d_out;

    dim3 gA(16, BB);
    kA<<<gA, 256>>>(q, keys, joints);
    kB<<<BB * NN, 256>>>(q, keys, out);
}